// round 10
// baseline (speedup 1.0000x reference)
#include <cuda_runtime.h>
#include <math.h>

#define BB 8192
#define DD 384
#define EE 1024
#define RR 8
#define HH 64
#define DPAD 18
#define SLOTS 6
#define GRID_UV (148 * SLOTS)   // 888 SM-affine slots (<=784 used)
#define GRID_MAIN 640
#define DC 64
#define XSTR 68
#define NROWS 24576             // 8192 ev rows + 16384 xu rows

typedef unsigned long long ull;

// ---------------- device scratch ----------------
__device__ float g_evt[RR * HH * EE];      // ev transposed [r][h][e]
__device__ float g_xu[BB * 2 * HH];        // normalized xu per code
__device__ float g_part[2 * NROWS * HH];   // split-K partials (12.6 MB)
__device__ float g_gw[BB * 2];
__device__ int   g_rofc[BB * 2];           // router of each code
__device__ int   g_cnt[RR];
__device__ int   g_list[RR * BB];
__device__ int   g_pcnt[64];
__device__ int   g_plist[64 * BB];
__device__ int   g_uvtile[GRID_UV];
__device__ int   g_ptile[GRID_MAIN];
__device__ float g_sumP[RR];
__device__ float g_sumM[RR];

// ---------------- f32x2 helpers ----------------
__device__ __forceinline__ ull pk2(float a, float b) {
    ull r; asm("mov.b64 %0, {%1,%2};" : "=l"(r) : "f"(a), "f"(b)); return r;
}
__device__ __forceinline__ void upk2(ull v, float& lo, float& hi) {
    asm("mov.b64 {%0,%1}, %2;" : "=f"(lo), "=f"(hi) : "l"(v));
}
__device__ __forceinline__ ull fma2(ull a, ull b, ull c) {
    ull d; asm("fma.rn.f32x2 %0, %1, %2, %3;" : "=l"(d) : "l"(a), "l"(b), "l"(c)); return d;
}

// ---------------- kernel 0: init ----------------
__global__ void k_init() {
    int t = threadIdx.x;
    if (t < RR) { g_cnt[t] = 0; g_sumP[t] = 0.f; g_sumM[t] = 0.f; }
    if (t < 64) g_pcnt[t] = 0;
}

// ---------------- kernel 1: gate ----------------
__global__ void __launch_bounds__(256) k_gate(const float* __restrict__ x,
                                              const float* __restrict__ gw,
                                              const float* __restrict__ gb) {
    __shared__ float sP[RR], sM[RR];
    int tid = threadIdx.x;
    if (tid < RR) { sP[tid] = 0.f; sM[tid] = 0.f; }
    __syncthreads();

    int warp = tid >> 5, lane = tid & 31;
    int b = blockIdx.x * 8 + warp;

    float acc[RR];
#pragma unroll
    for (int r = 0; r < RR; r++) acc[r] = 0.f;
    const float* xr = x + b * DD;
    for (int d = lane; d < DD; d += 32) {
        float xv = xr[d];
        const float4* g4 = (const float4*)(gw + d * RR);
        float4 a = g4[0], c = g4[1];
        acc[0] += xv * a.x; acc[1] += xv * a.y; acc[2] += xv * a.z; acc[3] += xv * a.w;
        acc[4] += xv * c.x; acc[5] += xv * c.y; acc[6] += xv * c.z; acc[7] += xv * c.w;
    }
#pragma unroll
    for (int r = 0; r < RR; r++)
#pragma unroll
        for (int o = 16; o; o >>= 1) acc[r] += __shfl_xor_sync(0xffffffffu, acc[r], o);

    if (lane == 0) {
        float lg[RR];
#pragma unroll
        for (int r = 0; r < RR; r++) lg[r] = acc[r] + gb[r];
        int i0 = 0; float v0 = lg[0];
#pragma unroll
        for (int r = 1; r < RR; r++) if (lg[r] > v0) { v0 = lg[r]; i0 = r; }
        int i1 = -1; float v1 = -3.0e38f;
#pragma unroll
        for (int r = 0; r < RR; r++) if (r != i0 && lg[r] > v1) { v1 = lg[r]; i1 = r; }

        float s = 0.f, pr[RR];
#pragma unroll
        for (int r = 0; r < RR; r++) { pr[r] = expf(lg[r] - v0); s += pr[r]; }
        float inv = 1.f / s;
#pragma unroll
        for (int r = 0; r < RR; r++) atomicAdd(&sP[r], pr[r] * inv);
        atomicAdd(&sM[i0], 1.f);
        atomicAdd(&sM[i1], 1.f);

        float e1 = expf(v1 - v0);
        float den = 1.f / (1.f + e1);
        g_gw[b * 2 + 0] = den;
        g_gw[b * 2 + 1] = e1 * den;
        g_rofc[b * 2 + 0] = i0;
        g_rofc[b * 2 + 1] = i1;

        int p0 = atomicAdd(&g_cnt[i0], 1); g_list[i0 * BB + p0] = b * 2 + 0;
        int p1 = atomicAdd(&g_cnt[i1], 1); g_list[i1 * BB + p1] = b * 2 + 1;

        int pid = i0 * 8 + i1;
        int pp = atomicAdd(&g_pcnt[pid], 1); g_plist[pid * BB + pp] = b;
    }
    __syncthreads();
    if (tid < RR) { atomicAdd(&g_sumP[tid], sP[tid]); atomicAdd(&g_sumM[tid], sM[tid]); }
}

// ---------------- kernel 2: scheduler (split-K, SM-affine scatter) ----------------
__global__ void k_sched() {
    __shared__ int list[GRID_UV];
    __shared__ int roff[RR], poff[64];
    int tid = threadIdx.x;
    for (int i = tid; i < GRID_UV; i += 256) list[i] = -1;
    for (int i = tid; i < GRID_MAIN; i += 256) g_ptile[i] = -1;
    __syncthreads();
    if (tid == 0) {
        int o = 256;     // xu entries start after 128 ev tiles x 2 halves
        for (int r = 0; r < RR; r++) { roff[r] = o; o += 2 * ((g_cnt[r] + 63) >> 6); }
        o = 0;
        for (int p = 0; p < 64; p++) { poff[p] = o; o += (g_pcnt[p] + 15) >> 4; }
    }
    __syncthreads();
    // ev entries: [0,256): tile = tid>>1, half = tid&1, class-grouped (r = tile>>4)
    if (tid < 256) {
        int tile = tid >> 1, kh = tid & 1;
        int r = tile >> 4, ti = tile & 15;
        list[tid] = (r << 24) | (kh << 23) | ti;
    }
    // xu entries
    if (tid < RR) {
        int r = tid;
        int n = (g_cnt[r] + 63) >> 6;
        for (int i = 0; i < n; i++) {
            list[roff[r] + 2 * i + 0] = (1 << 28) | (r << 24) | (0 << 23) | i;
            list[roff[r] + 2 * i + 1] = (1 << 28) | (r << 24) | (1 << 23) | i;
        }
    }
    // pair tiles for k_main
    if (tid >= 64 && tid < 128) {
        int p = tid - 64;
        int n = (g_pcnt[p] + 15) >> 4;
        for (int i = 0; i < n; i++) g_ptile[poff[p] + i] = (p << 16) | i;
    }
    __syncthreads();
    // SM-affine scatter: blocks with equal bid%148 land on the same SM (classic LUT)
    for (int bid = tid; bid < GRID_UV; bid += 256) {
        int sm = bid % 148, k = bid / 148;
        g_uvtile[bid] = list[sm * SLOTS + k];
    }
}

// ---------------- kernel 3: split-K ev/xu GEMM (128 thr, 64 rows x 64 h x 192 d) ----------------
__global__ void __launch_bounds__(128) k_uv(const float* __restrict__ x,
                                            const float* __restrict__ re,
                                            const float* __restrict__ Uw,
                                            const float* __restrict__ Vw) {
    __shared__ float xT[DC * XSTR];   // transposed x chunk [d][row]  17.4 KB
    __shared__ int   s_code[64];

    int info = g_uvtile[blockIdx.x];
    if (info < 0) return;
    int type = (info >> 28) & 1;
    int r    = (info >> 24) & 15;
    int kh   = (info >> 23) & 1;
    int tile = info & 0x7fffff;
    int tid = threadIdx.x;

    const float* W = (type == 0 ? Vw : Uw) + r * DD * HH;

    if (tid < 64) {
        if (type == 0) s_code[tid] = tile * 64 + tid;
        else {
            int cnt = g_cnt[r], base = tile * 64;
            s_code[tid] = (base + tid < cnt) ? g_list[r * BB + base + tid] : -1;
        }
    }
    __syncthreads();

    int w = tid >> 5, l = tid & 31;
    int hq = l & 15, rg = l >> 4;
    int h0 = hq * 4;
    int wrow = w * 16 + rg * 8;          // 8 rows (4 f32x2 pairs) per lane

    int srow = tid & 63, shalf = tid >> 6;
    const float* src;
    {
        int c = s_code[srow];
        if (type == 0) src = re + (long)c * DD;
        else           src = (c >= 0) ? (x + (long)(c >> 1) * DD) : (const float*)0;
    }

    ull acc[4][4];
#pragma unroll
    for (int a = 0; a < 4; a++)
#pragma unroll
        for (int b = 0; b < 4; b++) acc[a][b] = 0ULL;

    int dbase = kh * 192;
    for (int cc = 0; cc < 3; cc++) {
        int dc = dbase + cc * DC;
        if (src) {
#pragma unroll
            for (int i = 0; i < 8; i++) {
                int d = shalf * 32 + i * 4;
                float4 v = *(const float4*)(src + dc + d);
                xT[(d + 0) * XSTR + srow] = v.x; xT[(d + 1) * XSTR + srow] = v.y;
                xT[(d + 2) * XSTR + srow] = v.z; xT[(d + 3) * XSTR + srow] = v.w;
            }
        } else {
#pragma unroll
            for (int i = 0; i < 8; i++) {
                int d = shalf * 32 + i * 4;
                xT[(d + 0) * XSTR + srow] = 0.f; xT[(d + 1) * XSTR + srow] = 0.f;
                xT[(d + 2) * XSTR + srow] = 0.f; xT[(d + 3) * XSTR + srow] = 0.f;
            }
        }
        __syncthreads();

#pragma unroll 4
        for (int d = 0; d < DC; d++) {
            float4 wv = *(const float4*)(W + (dc + d) * HH + h0);
            ull b0 = pk2(wv.x, wv.x), b1 = pk2(wv.y, wv.y);
            ull b2 = pk2(wv.z, wv.z), b3 = pk2(wv.w, wv.w);
            const ull* xp = (const ull*)&xT[d * XSTR + wrow];
            ull x0 = xp[0], x1 = xp[1], x2 = xp[2], x3 = xp[3];
            acc[0][0] = fma2(x0, b0, acc[0][0]); acc[0][1] = fma2(x0, b1, acc[0][1]);
            acc[0][2] = fma2(x0, b2, acc[0][2]); acc[0][3] = fma2(x0, b3, acc[0][3]);
            acc[1][0] = fma2(x1, b0, acc[1][0]); acc[1][1] = fma2(x1, b1, acc[1][1]);
            acc[1][2] = fma2(x1, b2, acc[1][2]); acc[1][3] = fma2(x1, b3, acc[1][3]);
            acc[2][0] = fma2(x2, b0, acc[2][0]); acc[2][1] = fma2(x2, b1, acc[2][1]);
            acc[2][2] = fma2(x2, b2, acc[2][2]); acc[2][3] = fma2(x2, b3, acc[2][3]);
            acc[3][0] = fma2(x3, b0, acc[3][0]); acc[3][1] = fma2(x3, b1, acc[3][1]);
            acc[3][2] = fma2(x3, b2, acc[3][2]); acc[3][3] = fma2(x3, b3, acc[3][3]);
        }
        __syncthreads();
    }

    // store raw partials (no reduction, no norm)
    float* pb = g_part + (long)kh * NROWS * HH;
#pragma unroll
    for (int rp = 0; rp < 4; rp++) {
        float4 lo4, hi4;
        float lo, hi;
        upk2(acc[rp][0], lo, hi); lo4.x = lo; hi4.x = hi;
        upk2(acc[rp][1], lo, hi); lo4.y = lo; hi4.y = hi;
        upk2(acc[rp][2], lo, hi); lo4.z = lo; hi4.z = hi;
        upk2(acc[rp][3], lo, hi); lo4.w = lo; hi4.w = hi;
        int row0 = wrow + 2 * rp;
        if (type == 0) {
            long g0 = r * 1024 + tile * 64 + row0;
            *(float4*)(pb + g0 * HH + h0)       = lo4;
            *(float4*)(pb + (g0 + 1) * HH + h0) = hi4;
        } else {
            int c0 = s_code[row0], c1 = s_code[row0 + 1];
            if (c0 >= 0) *(float4*)(pb + (8192L + c0) * HH + h0) = lo4;
            if (c1 >= 0) *(float4*)(pb + (8192L + c1) * HH + h0) = hi4;
        }
    }
}

// ---------------- kernel 3b: finish ev (combine halves + bias + norm + transpose) ----------------
__global__ void __launch_bounds__(256) k_fin_ev(const float* __restrict__ Vb) {
    __shared__ float outT[HH * XSTR];   // [h][row]
    __shared__ float s_rn[64];
    int b = blockIdx.x;                 // 0..127
    int r = b >> 4, ebase = (b & 15) * 64;
    int tid = threadIdx.x;
    int row = tid >> 2, q = tid & 3;
    long grow = r * 1024 + ebase + row;
    const float4* p0 = (const float4*)(g_part + grow * HH);
    const float4* p1 = (const float4*)(g_part + ((long)NROWS + grow) * HH);
    const float4* bb = (const float4*)(Vb + r * HH);

    float ss = 0.f;
    float4 vals[4];
#pragma unroll
    for (int i = 0; i < 4; i++) {
        int hq4 = q * 4 + i;
        float4 a = p0[hq4], c = p1[hq4], bi = bb[hq4];
        float4 v = make_float4(a.x + c.x + bi.x, a.y + c.y + bi.y,
                               a.z + c.z + bi.z, a.w + c.w + bi.w);
        vals[i] = v;
        ss += v.x * v.x + v.y * v.y + v.z * v.z + v.w * v.w;
    }
    ss += __shfl_xor_sync(0xffffffffu, ss, 1);
    ss += __shfl_xor_sync(0xffffffffu, ss, 2);
    if (q == 0) s_rn[row] = 1.f / fmaxf(sqrtf(ss), 1e-12f);
#pragma unroll
    for (int i = 0; i < 4; i++) {
        int h = (q * 4 + i) * 4;
        outT[(h + 0) * XSTR + row] = vals[i].x;
        outT[(h + 1) * XSTR + row] = vals[i].y;
        outT[(h + 2) * XSTR + row] = vals[i].z;
        outT[(h + 3) * XSTR + row] = vals[i].w;
    }
    __syncthreads();
    int h = tid >> 2, qq = tid & 3;
    float* dst = g_evt + (r * HH + h) * EE + ebase + qq * 16;
#pragma unroll
    for (int i = 0; i < 4; i++) {
        int e = qq * 16 + i * 4;
        float4 o = make_float4(outT[h * XSTR + e + 0] * s_rn[e + 0],
                               outT[h * XSTR + e + 1] * s_rn[e + 1],
                               outT[h * XSTR + e + 2] * s_rn[e + 2],
                               outT[h * XSTR + e + 3] * s_rn[e + 3]);
        *(float4*)(dst + i * 4) = o;
    }
}

// ---------------- kernel 3c: finish xu (warp per code) ----------------
__global__ void __launch_bounds__(256) k_fin_xu(const float* __restrict__ Ub) {
    int w = threadIdx.x >> 5, lane = threadIdx.x & 31;
    int code = blockIdx.x * 8 + w;
    int r = g_rofc[code];
    long grow = 8192L + code;
    float2 a = ((const float2*)(g_part + grow * HH))[lane];
    float2 c = ((const float2*)(g_part + ((long)NROWS + grow) * HH))[lane];
    float2 bi = ((const float2*)(Ub + r * HH))[lane];
    float v0 = a.x + c.x + bi.x, v1 = a.y + c.y + bi.y;
    float ss = v0 * v0 + v1 * v1;
#pragma unroll
    for (int o = 16; o; o >>= 1) ss += __shfl_xor_sync(0xffffffffu, ss, o);
    float rn = 1.f / fmaxf(sqrtf(ss), 1e-12f);
    ((float2*)(g_xu + (long)code * HH))[lane] = make_float2(v0 * rn, v1 * rn);
}

// ---------------- kernel 4: pair-grouped scores + softmax + combine + sample ----------------
__global__ void __launch_bounds__(256, 2) k_main(const float* __restrict__ rnd,
                                                 float* __restrict__ out) {
    extern __shared__ float dyn[];
    float* p_s = dyn;                            // [16][1024]  64KB
    float* xu_s = dyn + 16 * EE;                 // [2][64][18] 9.2KB
    __shared__ int   s_b[16];
    __shared__ float s_w[2][16];
    __shared__ float red[8][16];
    __shared__ float rowstat[16];
    __shared__ float s_scale[16];

    int info = g_ptile[blockIdx.x];
    if (info < 0) return;
    int pid = info >> 16, base = (info & 0xffff) * 16;
    int r0 = pid >> 3, r1 = pid & 7;
    int cnt = g_pcnt[pid];
    int nt = min(16, cnt - base);
    int tid = threadIdx.x;

    if (tid < 16) {
        int b = (tid < nt) ? g_plist[pid * BB + base + tid] : -1;
        s_b[tid] = b;
        s_w[0][tid] = (b >= 0) ? g_gw[b * 2 + 0] : 0.f;
        s_w[1][tid] = (b >= 0) ? g_gw[b * 2 + 1] : 0.f;
    }
    __syncthreads();
    {
        int s = tid >> 7, c = (tid >> 3) & 15, h0 = (tid & 7) * 8;
        int b = s_b[c];
        float* dst = xu_s + s * (HH * DPAD);
        if (b >= 0) {
            const float4* src = (const float4*)(g_xu + (b * 2 + s) * HH + h0);
            float4 v0 = src[0], v1 = src[1];
            dst[(h0 + 0) * DPAD + c] = v0.x; dst[(h0 + 1) * DPAD + c] = v0.y;
            dst[(h0 + 2) * DPAD + c] = v0.z; dst[(h0 + 3) * DPAD + c] = v0.w;
            dst[(h0 + 4) * DPAD + c] = v1.x; dst[(h0 + 5) * DPAD + c] = v1.y;
            dst[(h0 + 6) * DPAD + c] = v1.z; dst[(h0 + 7) * DPAD + c] = v1.w;
        } else {
#pragma unroll
            for (int j = 0; j < 8; j++) dst[(h0 + j) * DPAD + c] = 0.f;
        }
    }
    __syncthreads();

    int e0 = tid * 4;
    int lane = tid & 31, w = tid >> 5;

    for (int ph = 0; ph < 2; ph++) {
        int r = ph ? r1 : r0;
        ull acc2[8][4];
#pragma unroll
        for (int tp = 0; tp < 8; tp++)
#pragma unroll
            for (int j = 0; j < 4; j++) acc2[tp][j] = 0ULL;

        const float* evr = g_evt + r * HH * EE;
        const float* xub = xu_s + ph * (HH * DPAD);
#pragma unroll 4
        for (int h = 0; h < HH; h++) {
            float4 ev4 = *(const float4*)(evr + h * EE + e0);
            ull bx = pk2(ev4.x, ev4.x);
            ull by = pk2(ev4.y, ev4.y);
            ull bz = pk2(ev4.z, ev4.z);
            ull bw = pk2(ev4.w, ev4.w);
            const ull* xp = (const ull*)(xub + h * DPAD);
#pragma unroll
            for (int tp = 0; tp < 8; tp++) {
                ull xs2 = xp[tp];
                acc2[tp][0] = fma2(xs2, bx, acc2[tp][0]);
                acc2[tp][1] = fma2(xs2, by, acc2[tp][1]);
                acc2[tp][2] = fma2(xs2, bz, acc2[tp][2]);
                acc2[tp][3] = fma2(xs2, bw, acc2[tp][3]);
            }
        }

        {
            float lmax[16];
#pragma unroll
            for (int t = 0; t < 16; t++) lmax[t] = -3.0e38f;
#pragma unroll
            for (int tp = 0; tp < 8; tp++)
#pragma unroll
                for (int j = 0; j < 4; j++) {
                    float lo, hi;
                    upk2(acc2[tp][j], lo, hi);
                    lmax[2 * tp]     = fmaxf(lmax[2 * tp], lo);
                    lmax[2 * tp + 1] = fmaxf(lmax[2 * tp + 1], hi);
                }
#pragma unroll
            for (int t = 0; t < 16; t++)
#pragma unroll
                for (int o = 16; o; o >>= 1)
                    lmax[t] = fmaxf(lmax[t], __shfl_xor_sync(0xffffffffu, lmax[t], o));
            if (lane == 0)
#pragma unroll
                for (int t = 0; t < 16; t++) red[w][t] = lmax[t];
        }
        __syncthreads();
        if (tid < 16) {
            float m = red[0][tid];
#pragma unroll
            for (int ww = 1; ww < 8; ww++) m = fmaxf(m, red[ww][tid]);
            rowstat[tid] = m;
        }
        __syncthreads();

        {
            float lsum[16];
#pragma unroll
            for (int t = 0; t < 16; t++) lsum[t] = 0.f;
#pragma unroll
            for (int tp = 0; tp < 8; tp++) {
                float m0 = rowstat[2 * tp], m1 = rowstat[2 * tp + 1];
#pragma unroll
                for (int j = 0; j < 4; j++) {
                    float lo, hi;
                    upk2(acc2[tp][j], lo, hi);
                    float elo = __expf(lo - m0);
                    float ehi = __expf(hi - m1);
                    lsum[2 * tp]     += elo;
                    lsum[2 * tp + 1] += ehi;
                    acc2[tp][j] = pk2(elo, ehi);
                }
            }
#pragma unroll
            for (int t = 0; t < 16; t++)
#pragma unroll
                for (int o = 16; o; o >>= 1)
                    lsum[t] += __shfl_xor_sync(0xffffffffu, lsum[t], o);
            if (lane == 0)
#pragma unroll
                for (int t = 0; t < 16; t++) red[w][t] = lsum[t];
        }
        __syncthreads();
        if (tid < 16) {
            float s = 0.f;
#pragma unroll
            for (int ww = 0; ww < 8; ww++) s += red[ww][tid];
            s_scale[tid] = s_w[ph][tid] / s;
        }
        __syncthreads();

#pragma unroll
        for (int tp = 0; tp < 8; tp++) {
            int t0 = 2 * tp, t1 = 2 * tp + 1;
            float sc0 = s_scale[t0], sc1 = s_scale[t1];
            float4 olo, ohi;
            float lo, hi;
            upk2(acc2[tp][0], lo, hi); olo.x = lo * sc0; ohi.x = hi * sc1;
            upk2(acc2[tp][1], lo, hi); olo.y = lo * sc0; ohi.y = hi * sc1;
            upk2(acc2[tp][2], lo, hi); olo.z = lo * sc0; ohi.z = hi * sc1;
            upk2(acc2[tp][3], lo, hi); olo.w = lo * sc0; ohi.w = hi * sc1;
            float4* d0 = (float4*)(p_s + t0 * EE + e0);
            float4* d1 = (float4*)(p_s + t1 * EE + e0);
            if (ph == 0) {
                *d0 = olo; *d1 = ohi;
            } else {
                float4 a = *d0, c = *d1;
                a.x += olo.x; a.y += olo.y; a.z += olo.z; a.w += olo.w;
                c.x += ohi.x; c.y += ohi.y; c.z += ohi.z; c.w += ohi.w;
                *d0 = a; *d1 = c;
            }
        }
        __syncthreads();
    }

#pragma unroll
    for (int k = 0; k < 2; k++) {
        int t = w * 2 + k;
        int b = s_b[t];
        if (b < 0) continue;
        float rv = rnd[b];
        int ebase2 = lane * 32;
        float v[32];
        const float4* pr = (const float4*)(p_s + t * EE + ebase2);
#pragma unroll
        for (int q = 0; q < 8; q++) {
            float4 f = pr[q];
            v[q * 4 + 0] = f.x; v[q * 4 + 1] = f.y; v[q * 4 + 2] = f.z; v[q * 4 + 3] = f.w;
        }
        float lsum = 0.f;
#pragma unroll
        for (int i = 0; i < 32; i++) lsum += v[i];
        float sc = lsum;
#pragma unroll
        for (int o = 1; o < 32; o <<= 1) {
            float u = __shfl_up_sync(0xffffffffu, sc, o);
            if (lane >= o) sc += u;
        }
        float run = sc - lsum;
        int cand = 0x7fffffff;
        float pv = 0.f;
#pragma unroll
        for (int i = 0; i < 32; i++) {
            run += v[i];
            if (cand == 0x7fffffff && run > rv) { cand = ebase2 + i; pv = v[i]; }
        }
        unsigned mask = __ballot_sync(0xffffffffu, cand != 0x7fffffff);
        if (mask == 0) {
            if (lane == 0) { out[b] = 0.f; out[BB + b] = logf(v[0]); }
        } else {
            int firstlane = __ffs(mask) - 1;
            if (lane == firstlane) { out[b] = (float)cand; out[BB + b] = logf(pv); }
        }
    }
}

// ---------------- kernel 5: aux ----------------
__global__ void k_aux(float* __restrict__ out) {
    if (threadIdx.x == 0 && blockIdx.x == 0) {
        float s = 0.f;
#pragma unroll
        for (int r = 0; r < RR; r++) s += g_sumP[r] * g_sumM[r];
        out[2 * BB] = (float)RR * 0.05f * s / ((float)BB * (float)BB);
    }
}

// ---------------- launch ----------------
extern "C" void kernel_launch(void* const* d_in, const int* in_sizes, int n_in,
                              void* d_out, int out_size) {
    const float* x   = (const float*)d_in[0];
    const float* re  = (const float*)d_in[1];
    const float* rnd = (const float*)d_in[2];
    const float* gw  = (const float*)d_in[3];
    const float* gb  = (const float*)d_in[4];
    const float* Uw  = (const float*)d_in[5];
    const float* Ub  = (const float*)d_in[6];
    const float* Vw  = (const float*)d_in[7];
    const float* Vb  = (const float*)d_in[8];
    float* out = (float*)d_out;

    const int dyn_bytes = (16 * EE + 2 * HH * DPAD) * sizeof(float);  // ~74.8KB
    cudaFuncSetAttribute(k_main, cudaFuncAttributeMaxDynamicSharedMemorySize, dyn_bytes);

    k_init<<<1, 128>>>();
    k_gate<<<BB / 8, 256>>>(x, gw, gb);
    k_sched<<<1, 256>>>();
    k_uv<<<GRID_UV, 128>>>(x, re, Uw, Vw);
    k_fin_ev<<<128, 256>>>(Vb);
    k_fin_xu<<<BB * 2 / 8, 256>>>(Ub);
    k_main<<<GRID_MAIN, 256, dyn_bytes>>>(rnd, out);
    k_aux<<<1, 32>>>(out);
}

// round 12
// speedup vs baseline: 1.0330x; 1.0330x over previous
#include <cuda_runtime.h>
#include <math.h>

#define BB 8192
#define DD 384
#define EE 1024
#define RR 8
#define HH 64
#define DPAD 18
#define SLOTS 6
#define GRID_UV (148 * SLOTS)   // 888 SM-affine slots (<=784 used)
#define GRID_MAIN 640
#define DC 64
#define XSTR 68
#define NROWS 24576             // 8192 ev rows + 16384 xu rows

typedef unsigned long long ull;

// ---------------- device scratch ----------------
__device__ float g_evt[RR * HH * EE];      // ev transposed [r][h][e]
__device__ float g_part[2 * NROWS * HH];   // split-K partials (12.6 MB)
__device__ float g_gw[BB * 2];
__device__ int   g_cnt[RR];
__device__ int   g_list[RR * BB];
__device__ int   g_pcnt[64];
__device__ int   g_plist[64 * BB];
__device__ int   g_uvtile[GRID_UV];
__device__ int   g_ptile[GRID_MAIN];
__device__ float g_sumP[RR];
__device__ float g_sumM[RR];

// ---------------- f32x2 helpers ----------------
__device__ __forceinline__ ull pk2(float a, float b) {
    ull r; asm("mov.b64 %0, {%1,%2};" : "=l"(r) : "f"(a), "f"(b)); return r;
}
__device__ __forceinline__ void upk2(ull v, float& lo, float& hi) {
    asm("mov.b64 {%0,%1}, %2;" : "=f"(lo), "=f"(hi) : "l"(v));
}
__device__ __forceinline__ ull fma2(ull a, ull b, ull c) {
    ull d; asm("fma.rn.f32x2 %0, %1, %2, %3;" : "=l"(d) : "l"(a), "l"(b), "l"(c)); return d;
}

// ---------------- kernel 0: init ----------------
__global__ void k_init() {
    int t = threadIdx.x;
    if (t < RR) { g_cnt[t] = 0; g_sumP[t] = 0.f; g_sumM[t] = 0.f; }
    if (t < 64) g_pcnt[t] = 0;
}

// ---------------- kernel 1: gate ----------------
__global__ void __launch_bounds__(256) k_gate(const float* __restrict__ x,
                                              const float* __restrict__ gw,
                                              const float* __restrict__ gb) {
    __shared__ float sP[RR], sM[RR];
    int tid = threadIdx.x;
    if (tid < RR) { sP[tid] = 0.f; sM[tid] = 0.f; }
    __syncthreads();

    int warp = tid >> 5, lane = tid & 31;
    int b = blockIdx.x * 8 + warp;

    float acc[RR];
#pragma unroll
    for (int r = 0; r < RR; r++) acc[r] = 0.f;
    const float* xr = x + b * DD;
    for (int d = lane; d < DD; d += 32) {
        float xv = xr[d];
        const float4* g4 = (const float4*)(gw + d * RR);
        float4 a = g4[0], c = g4[1];
        acc[0] += xv * a.x; acc[1] += xv * a.y; acc[2] += xv * a.z; acc[3] += xv * a.w;
        acc[4] += xv * c.x; acc[5] += xv * c.y; acc[6] += xv * c.z; acc[7] += xv * c.w;
    }
#pragma unroll
    for (int r = 0; r < RR; r++)
#pragma unroll
        for (int o = 16; o; o >>= 1) acc[r] += __shfl_xor_sync(0xffffffffu, acc[r], o);

    if (lane == 0) {
        float lg[RR];
#pragma unroll
        for (int r = 0; r < RR; r++) lg[r] = acc[r] + gb[r];
        int i0 = 0; float v0 = lg[0];
#pragma unroll
        for (int r = 1; r < RR; r++) if (lg[r] > v0) { v0 = lg[r]; i0 = r; }
        int i1 = -1; float v1 = -3.0e38f;
#pragma unroll
        for (int r = 0; r < RR; r++) if (r != i0 && lg[r] > v1) { v1 = lg[r]; i1 = r; }

        float s = 0.f, pr[RR];
#pragma unroll
        for (int r = 0; r < RR; r++) { pr[r] = expf(lg[r] - v0); s += pr[r]; }
        float inv = 1.f / s;
#pragma unroll
        for (int r = 0; r < RR; r++) atomicAdd(&sP[r], pr[r] * inv);
        atomicAdd(&sM[i0], 1.f);
        atomicAdd(&sM[i1], 1.f);

        float e1 = expf(v1 - v0);
        float den = 1.f / (1.f + e1);
        g_gw[b * 2 + 0] = den;
        g_gw[b * 2 + 1] = e1 * den;

        int p0 = atomicAdd(&g_cnt[i0], 1); g_list[i0 * BB + p0] = b * 2 + 0;
        int p1 = atomicAdd(&g_cnt[i1], 1); g_list[i1 * BB + p1] = b * 2 + 1;

        int pid = i0 * 8 + i1;
        int pp = atomicAdd(&g_pcnt[pid], 1); g_plist[pid * BB + pp] = b;
    }
    __syncthreads();
    if (tid < RR) { atomicAdd(&g_sumP[tid], sP[tid]); atomicAdd(&g_sumM[tid], sM[tid]); }
}

// ---------------- kernel 2: scheduler (split-K, SM-affine scatter) ----------------
__global__ void k_sched() {
    __shared__ int list[GRID_UV];
    __shared__ int roff[RR], poff[64];
    int tid = threadIdx.x;
    for (int i = tid; i < GRID_UV; i += 256) list[i] = -1;
    for (int i = tid; i < GRID_MAIN; i += 256) g_ptile[i] = -1;
    __syncthreads();
    if (tid == 0) {
        int o = 256;     // xu entries start after 128 ev tiles x 2 halves
        for (int r = 0; r < RR; r++) { roff[r] = o; o += 2 * ((g_cnt[r] + 63) >> 6); }
        o = 0;
        for (int p = 0; p < 64; p++) { poff[p] = o; o += (g_pcnt[p] + 15) >> 4; }
    }
    __syncthreads();
    if (tid < 256) {
        int tile = tid >> 1, kh = tid & 1;
        int r = tile >> 4, ti = tile & 15;
        list[tid] = (r << 24) | (kh << 23) | ti;
    }
    if (tid < RR) {
        int r = tid;
        int n = (g_cnt[r] + 63) >> 6;
        for (int i = 0; i < n; i++) {
            list[roff[r] + 2 * i + 0] = (1 << 28) | (r << 24) | (0 << 23) | i;
            list[roff[r] + 2 * i + 1] = (1 << 28) | (r << 24) | (1 << 23) | i;
        }
    }
    if (tid >= 64 && tid < 128) {
        int p = tid - 64;
        int n = (g_pcnt[p] + 15) >> 4;
        for (int i = 0; i < n; i++) g_ptile[poff[p] + i] = (p << 16) | i;
    }
    __syncthreads();
    for (int bid = tid; bid < GRID_UV; bid += 256) {
        int sm = bid % 148, k = bid / 148;
        g_uvtile[bid] = list[sm * SLOTS + k];
    }
}

// ---------------- kernel 3: split-K ev/xu GEMM (128 thr, 64 rows x 64 h x 192 d) ----------------
__global__ void __launch_bounds__(128) k_uv(const float* __restrict__ x,
                                            const float* __restrict__ re,
                                            const float* __restrict__ Uw,
                                            const float* __restrict__ Vw) {
    __shared__ float xT[DC * XSTR];   // transposed x chunk [d][row]  17.4 KB
    __shared__ int   s_code[64];

    int info = g_uvtile[blockIdx.x];
    if (info < 0) return;
    int type = (info >> 28) & 1;
    int r    = (info >> 24) & 15;
    int kh   = (info >> 23) & 1;
    int tile = info & 0x7fffff;
    int tid = threadIdx.x;

    const float* W = (type == 0 ? Vw : Uw) + r * DD * HH;

    if (tid < 64) {
        if (type == 0) s_code[tid] = tile * 64 + tid;
        else {
            int cnt = g_cnt[r], base = tile * 64;
            s_code[tid] = (base + tid < cnt) ? g_list[r * BB + base + tid] : -1;
        }
    }
    __syncthreads();

    int w = tid >> 5, l = tid & 31;
    int hq = l & 15, rg = l >> 4;
    int h0 = hq * 4;
    int wrow = w * 16 + rg * 8;          // 8 rows (4 f32x2 pairs) per lane

    int srow = tid & 63, shalf = tid >> 6;
    const float* src;
    {
        int c = s_code[srow];
        if (type == 0) src = re + (long)c * DD;
        else           src = (c >= 0) ? (x + (long)(c >> 1) * DD) : (const float*)0;
    }

    ull acc[4][4];
#pragma unroll
    for (int a = 0; a < 4; a++)
#pragma unroll
        for (int b = 0; b < 4; b++) acc[a][b] = 0ULL;

    int dbase = kh * 192;
    for (int cc = 0; cc < 3; cc++) {
        int dc = dbase + cc * DC;
        if (src) {
#pragma unroll
            for (int i = 0; i < 8; i++) {
                int d = shalf * 32 + i * 4;
                float4 v = __ldcs((const float4*)(src + dc + d));   // evict-first: keep W in L1
                xT[(d + 0) * XSTR + srow] = v.x; xT[(d + 1) * XSTR + srow] = v.y;
                xT[(d + 2) * XSTR + srow] = v.z; xT[(d + 3) * XSTR + srow] = v.w;
            }
        } else {
#pragma unroll
            for (int i = 0; i < 8; i++) {
                int d = shalf * 32 + i * 4;
                xT[(d + 0) * XSTR + srow] = 0.f; xT[(d + 1) * XSTR + srow] = 0.f;
                xT[(d + 2) * XSTR + srow] = 0.f; xT[(d + 3) * XSTR + srow] = 0.f;
            }
        }
        __syncthreads();

#pragma unroll 8
        for (int d = 0; d < DC; d++) {
            float4 wv = *(const float4*)(W + (dc + d) * HH + h0);
            ull b0 = pk2(wv.x, wv.x), b1 = pk2(wv.y, wv.y);
            ull b2 = pk2(wv.z, wv.z), b3 = pk2(wv.w, wv.w);
            const ull* xp = (const ull*)&xT[d * XSTR + wrow];
            ull x0 = xp[0], x1 = xp[1], x2 = xp[2], x3 = xp[3];
            acc[0][0] = fma2(x0, b0, acc[0][0]); acc[0][1] = fma2(x0, b1, acc[0][1]);
            acc[0][2] = fma2(x0, b2, acc[0][2]); acc[0][3] = fma2(x0, b3, acc[0][3]);
            acc[1][0] = fma2(x1, b0, acc[1][0]); acc[1][1] = fma2(x1, b1, acc[1][1]);
            acc[1][2] = fma2(x1, b2, acc[1][2]); acc[1][3] = fma2(x1, b3, acc[1][3]);
            acc[2][0] = fma2(x2, b0, acc[2][0]); acc[2][1] = fma2(x2, b1, acc[2][1]);
            acc[2][2] = fma2(x2, b2, acc[2][2]); acc[2][3] = fma2(x2, b3, acc[2][3]);
            acc[3][0] = fma2(x3, b0, acc[3][0]); acc[3][1] = fma2(x3, b1, acc[3][1]);
            acc[3][2] = fma2(x3, b2, acc[3][2]); acc[3][3] = fma2(x3, b3, acc[3][3]);
        }
        __syncthreads();
    }

    // store raw partials (no reduction, no norm)
    float* pb = g_part + (long)kh * NROWS * HH;
#pragma unroll
    for (int rp = 0; rp < 4; rp++) {
        float4 lo4, hi4;
        float lo, hi;
        upk2(acc[rp][0], lo, hi); lo4.x = lo; hi4.x = hi;
        upk2(acc[rp][1], lo, hi); lo4.y = lo; hi4.y = hi;
        upk2(acc[rp][2], lo, hi); lo4.z = lo; hi4.z = hi;
        upk2(acc[rp][3], lo, hi); lo4.w = lo; hi4.w = hi;
        int row0 = wrow + 2 * rp;
        if (type == 0) {
            long g0 = r * 1024 + tile * 64 + row0;
            *(float4*)(pb + g0 * HH + h0)       = lo4;
            *(float4*)(pb + (g0 + 1) * HH + h0) = hi4;
        } else {
            int c0 = s_code[row0], c1 = s_code[row0 + 1];
            if (c0 >= 0) *(float4*)(pb + (8192L + c0) * HH + h0) = lo4;
            if (c1 >= 0) *(float4*)(pb + (8192L + c1) * HH + h0) = hi4;
        }
    }
}

// ---------------- kernel 3b: finish ev (combine halves + bias + norm + transpose) ----------------
__global__ void __launch_bounds__(256) k_fin_ev(const float* __restrict__ Vb) {
    __shared__ float outT[HH * XSTR];   // [h][row]
    __shared__ float s_rn[64];
    int b = blockIdx.x;                 // 0..127
    int r = b >> 4, ebase = (b & 15) * 64;
    int tid = threadIdx.x;
    int row = tid >> 2, q = tid & 3;
    long grow = r * 1024 + ebase + row;
    const float4* p0 = (const float4*)(g_part + grow * HH);
    const float4* p1 = (const float4*)(g_part + ((long)NROWS + grow) * HH);
    const float4* bb = (const float4*)(Vb + r * HH);

    float ss = 0.f;
    float4 vals[4];
#pragma unroll
    for (int i = 0; i < 4; i++) {
        int hq4 = q * 4 + i;
        float4 a = p0[hq4], c = p1[hq4], bi = bb[hq4];
        float4 v = make_float4(a.x + c.x + bi.x, a.y + c.y + bi.y,
                               a.z + c.z + bi.z, a.w + c.w + bi.w);
        vals[i] = v;
        ss += v.x * v.x + v.y * v.y + v.z * v.z + v.w * v.w;
    }
    ss += __shfl_xor_sync(0xffffffffu, ss, 1);
    ss += __shfl_xor_sync(0xffffffffu, ss, 2);
    if (q == 0) s_rn[row] = 1.f / fmaxf(sqrtf(ss), 1e-12f);
#pragma unroll
    for (int i = 0; i < 4; i++) {
        int h = (q * 4 + i) * 4;
        outT[(h + 0) * XSTR + row] = vals[i].x;
        outT[(h + 1) * XSTR + row] = vals[i].y;
        outT[(h + 2) * XSTR + row] = vals[i].z;
        outT[(h + 3) * XSTR + row] = vals[i].w;
    }
    __syncthreads();
    int h = tid >> 2, qq = tid & 3;
    float* dst = g_evt + (r * HH + h) * EE + ebase + qq * 16;
#pragma unroll
    for (int i = 0; i < 4; i++) {
        int e = qq * 16 + i * 4;
        float4 o = make_float4(outT[h * XSTR + e + 0] * s_rn[e + 0],
                               outT[h * XSTR + e + 1] * s_rn[e + 1],
                               outT[h * XSTR + e + 2] * s_rn[e + 2],
                               outT[h * XSTR + e + 3] * s_rn[e + 3]);
        *(float4*)(dst + i * 4) = o;
    }
}

// ---------------- kernel 4: pair-grouped scores + softmax + combine + sample ----------------
// xu finishing (combine split-K halves + bias + l2norm) folded into staging;
// row-max pass removed: xu, ev unit vectors => scores in [-1,1], exp overflow-safe.
__global__ void __launch_bounds__(256, 2) k_main(const float* __restrict__ rnd,
                                                 const float* __restrict__ Ub,
                                                 float* __restrict__ out) {
    extern __shared__ float dyn[];
    float* p_s = dyn;                            // [16][1024]  64KB
    float* xu_s = dyn + 16 * EE;                 // [2][64][18] 9.2KB
    __shared__ int   s_b[16];
    __shared__ float s_w[2][16];
    __shared__ float red[8][16];
    __shared__ float s_scale[16];

    int info = g_ptile[blockIdx.x];
    if (info < 0) return;
    int pid = info >> 16, base = (info & 0xffff) * 16;
    int r0 = pid >> 3, r1 = pid & 7;
    int cnt = g_pcnt[pid];
    int nt = min(16, cnt - base);
    int tid = threadIdx.x;

    if (tid < 16) {
        int b = (tid < nt) ? g_plist[pid * BB + base + tid] : -1;
        s_b[tid] = b;
        s_w[0][tid] = (b >= 0) ? g_gw[b * 2 + 0] : 0.f;
        s_w[1][tid] = (b >= 0) ? g_gw[b * 2 + 1] : 0.f;
    }
    __syncthreads();
    {   // stage xu: combine split-K partials + bias, l2-normalize (8 threads/code)
        int s = tid >> 7, c = (tid >> 3) & 15, j = tid & 7, h0 = j * 8;
        int b = s_b[c];
        float* dst = xu_s + s * (HH * DPAD);
        float4 v0 = make_float4(0.f, 0.f, 0.f, 0.f), v1 = v0;
        float ss = 0.f;
        if (b >= 0) {
            long code = (long)b * 2 + s;
            const float4* p0 = (const float4*)(g_part + (8192L + code) * HH + h0);
            const float4* p1 = (const float4*)(g_part + ((long)NROWS + 8192L + code) * HH + h0);
            int rr = s ? r1 : r0;
            const float4* bb4 = (const float4*)(Ub + rr * HH + h0);
            float4 a0 = p0[0], a1 = p0[1];
            float4 c0 = p1[0], c1 = p1[1];
            float4 b0 = bb4[0], b1 = bb4[1];
            v0 = make_float4(a0.x + c0.x + b0.x, a0.y + c0.y + b0.y,
                             a0.z + c0.z + b0.z, a0.w + c0.w + b0.w);
            v1 = make_float4(a1.x + c1.x + b1.x, a1.y + c1.y + b1.y,
                             a1.z + c1.z + b1.z, a1.w + c1.w + b1.w);
            ss = v0.x * v0.x + v0.y * v0.y + v0.z * v0.z + v0.w * v0.w
               + v1.x * v1.x + v1.y * v1.y + v1.z * v1.z + v1.w * v1.w;
        }
#pragma unroll
        for (int o = 1; o < 8; o <<= 1) ss += __shfl_xor_sync(0xffffffffu, ss, o);
        float rn = 1.f / fmaxf(sqrtf(ss), 1e-12f);
        dst[(h0 + 0) * DPAD + c] = v0.x * rn; dst[(h0 + 1) * DPAD + c] = v0.y * rn;
        dst[(h0 + 2) * DPAD + c] = v0.z * rn; dst[(h0 + 3) * DPAD + c] = v0.w * rn;
        dst[(h0 + 4) * DPAD + c] = v1.x * rn; dst[(h0 + 5) * DPAD + c] = v1.y * rn;
        dst[(h0 + 6) * DPAD + c] = v1.z * rn; dst[(h0 + 7) * DPAD + c] = v1.w * rn;
    }
    __syncthreads();

    int e0 = tid * 4;
    int lane = tid & 31, w = tid >> 5;

    for (int ph = 0; ph < 2; ph++) {
        int r = ph ? r1 : r0;
        ull acc2[8][4];
#pragma unroll
        for (int tp = 0; tp < 8; tp++)
#pragma unroll
            for (int j = 0; j < 4; j++) acc2[tp][j] = 0ULL;

        const float* evr = g_evt + r * HH * EE;
        const float* xub = xu_s + ph * (HH * DPAD);
#pragma unroll 4
        for (int h = 0; h < HH; h++) {
            float4 ev4 = *(const float4*)(evr + h * EE + e0);
            ull bx = pk2(ev4.x, ev4.x);
            ull by = pk2(ev4.y, ev4.y);
            ull bz = pk2(ev4.z, ev4.z);
            ull bw = pk2(ev4.w, ev4.w);
            const ull* xp = (const ull*)(xub + h * DPAD);
#pragma unroll
            for (int tp = 0; tp < 8; tp++) {
                ull xs2 = xp[tp];
                acc2[tp][0] = fma2(xs2, bx, acc2[tp][0]);
                acc2[tp][1] = fma2(xs2, by, acc2[tp][1]);
                acc2[tp][2] = fma2(xs2, bz, acc2[tp][2]);
                acc2[tp][3] = fma2(xs2, bw, acc2[tp][3]);
            }
        }

        // exp + row sum (no max subtraction needed: scores bounded by 1)
        {
            float lsum[16];
#pragma unroll
            for (int t = 0; t < 16; t++) lsum[t] = 0.f;
#pragma unroll
            for (int tp = 0; tp < 8; tp++) {
#pragma unroll
                for (int j = 0; j < 4; j++) {
                    float lo, hi;
                    upk2(acc2[tp][j], lo, hi);
                    float elo = __expf(lo);
                    float ehi = __expf(hi);
                    lsum[2 * tp]     += elo;
                    lsum[2 * tp + 1] += ehi;
                    acc2[tp][j] = pk2(elo, ehi);
                }
            }
#pragma unroll
            for (int t = 0; t < 16; t++)
#pragma unroll
                for (int o = 16; o; o >>= 1)
                    lsum[t] += __shfl_xor_sync(0xffffffffu, lsum[t], o);
            if (lane == 0)
#pragma unroll
                for (int t = 0; t < 16; t++) red[w][t] = lsum[t];
        }
        __syncthreads();
        if (tid < 16) {
            float s = 0.f;
#pragma unroll
            for (int ww = 0; ww < 8; ww++) s += red[ww][tid];
            s_scale[tid] = s_w[ph][tid] / s;
        }
        __syncthreads();

#pragma unroll
        for (int tp = 0; tp < 8; tp++) {
            int t0 = 2 * tp, t1 = 2 * tp + 1;
            float sc0 = s_scale[t0], sc1 = s_scale[t1];
            float4 olo, ohi;
            float lo, hi;
            upk2(acc2[tp][0], lo, hi); olo.x = lo * sc0; ohi.x = hi * sc1;
            upk2(acc2[tp][1], lo, hi); olo.y = lo * sc0; ohi.y = hi * sc1;
            upk2(acc2[tp][2], lo, hi); olo.z = lo * sc0; ohi.z = hi * sc1;
            upk2(acc2[tp][3], lo, hi); olo.w = lo * sc0; ohi.w = hi * sc1;
            float4* d0 = (float4*)(p_s + t0 * EE + e0);
            float4* d1 = (float4*)(p_s + t1 * EE + e0);
            if (ph == 0) {
                *d0 = olo; *d1 = ohi;
            } else {
                float4 a = *d0, c = *d1;
                a.x += olo.x; a.y += olo.y; a.z += olo.z; a.w += olo.w;
                c.x += ohi.x; c.y += ohi.y; c.z += ohi.z; c.w += ohi.w;
                *d0 = a; *d1 = c;
            }
        }
        __syncthreads();
    }

    // sampling: warp w handles tokens 2w, 2w+1
#pragma unroll
    for (int k = 0; k < 2; k++) {
        int t = w * 2 + k;
        int b = s_b[t];
        if (b < 0) continue;
        float rv = rnd[b];
        int ebase2 = lane * 32;
        float v[32];
        const float4* pr = (const float4*)(p_s + t * EE + ebase2);
#pragma unroll
        for (int q = 0; q < 8; q++) {
            float4 f = pr[q];
            v[q * 4 + 0] = f.x; v[q * 4 + 1] = f.y; v[q * 4 + 2] = f.z; v[q * 4 + 3] = f.w;
        }
        float lsum = 0.f;
#pragma unroll
        for (int i = 0; i < 32; i++) lsum += v[i];
        float sc = lsum;
#pragma unroll
        for (int o = 1; o < 32; o <<= 1) {
            float u = __shfl_up_sync(0xffffffffu, sc, o);
            if (lane >= o) sc += u;
        }
        float run = sc - lsum;
        int cand = 0x7fffffff;
        float pv = 0.f;
#pragma unroll
        for (int i = 0; i < 32; i++) {
            run += v[i];
            if (cand == 0x7fffffff && run > rv) { cand = ebase2 + i; pv = v[i]; }
        }
        unsigned mask = __ballot_sync(0xffffffffu, cand != 0x7fffffff);
        if (mask == 0) {
            if (lane == 0) { out[b] = 0.f; out[BB + b] = logf(v[0]); }
        } else {
            int firstlane = __ffs(mask) - 1;
            if (lane == firstlane) { out[b] = (float)cand; out[BB + b] = logf(pv); }
        }
    }
}

// ---------------- kernel 5: aux ----------------
__global__ void k_aux(float* __restrict__ out) {
    if (threadIdx.x == 0 && blockIdx.x == 0) {
        float s = 0.f;
#pragma unroll
        for (int r = 0; r < RR; r++) s += g_sumP[r] * g_sumM[r];
        out[2 * BB] = (float)RR * 0.05f * s / ((float)BB * (float)BB);
    }
}

// ---------------- launch ----------------
extern "C" void kernel_launch(void* const* d_in, const int* in_sizes, int n_in,
                              void* d_out, int out_size) {
    const float* x   = (const float*)d_in[0];
    const float* re  = (const float*)d_in[1];
    const float* rnd = (const float*)d_in[2];
    const float* gw  = (const float*)d_in[3];
    const float* gb  = (const float*)d_in[4];
    const float* Uw  = (const float*)d_in[5];
    const float* Ub  = (const float*)d_in[6];
    const float* Vw  = (const float*)d_in[7];
    const float* Vb  = (const float*)d_in[8];
    float* out = (float*)d_out;

    const int dyn_bytes = (16 * EE + 2 * HH * DPAD) * sizeof(float);  // ~74.8KB
    cudaFuncSetAttribute(k_main, cudaFuncAttributeMaxDynamicSharedMemorySize, dyn_bytes);

    k_init<<<1, 128>>>();
    k_gate<<<BB / 8, 256>>>(x, gw, gb);
    k_sched<<<1, 256>>>();
    k_uv<<<GRID_UV, 128>>>(x, re, Uw, Vw);
    k_fin_ev<<<128, 256>>>(Vb);
    k_main<<<GRID_MAIN, 256, dyn_bytes>>>(rnd, Ub, out);
    k_aux<<<1, 32>>>(out);
}

// round 14
// speedup vs baseline: 1.0878x; 1.0531x over previous
#include <cuda_runtime.h>
#include <math.h>

#define BB 8192
#define DD 384
#define EE 1024
#define RR 8
#define HH 64
#define DPAD 20             // 80B rows: 16B-aligned for LDS.128
#define SLOTS 6
#define GRID_UV (148 * SLOTS)   // 888 SM-affine slots (<=784 used)
#define GRID_MAIN 640
#define DC 64
#define XSTR 68
#define NROWS 24576             // 8192 ev rows + 16384 xu rows

typedef unsigned long long ull;

// ---------------- device scratch ----------------
__device__ float g_evt[RR * HH * EE];      // ev transposed [r][h][e]
__device__ float g_part[2 * NROWS * HH];   // split-K partials (12.6 MB)
__device__ float g_gw[BB * 2];
__device__ int   g_cnt[RR];
__device__ int   g_list[RR * BB];
__device__ int   g_pcnt[64];
__device__ int   g_plist[64 * BB];
__device__ int   g_uvtile[GRID_UV];
__device__ int   g_ptile[GRID_MAIN];
__device__ float g_sumP[RR];
__device__ float g_sumM[RR];

// ---------------- f32x2 helpers ----------------
__device__ __forceinline__ ull pk2(float a, float b) {
    ull r; asm("mov.b64 %0, {%1,%2};" : "=l"(r) : "f"(a), "f"(b)); return r;
}
__device__ __forceinline__ void upk2(ull v, float& lo, float& hi) {
    asm("mov.b64 {%0,%1}, %2;" : "=f"(lo), "=f"(hi) : "l"(v));
}
__device__ __forceinline__ ull fma2(ull a, ull b, ull c) {
    ull d; asm("fma.rn.f32x2 %0, %1, %2, %3;" : "=l"(d) : "l"(a), "l"(b), "l"(c)); return d;
}

// ---------------- kernel 0: init ----------------
__global__ void k_init() {
    int t = threadIdx.x;
    if (t < RR) { g_cnt[t] = 0; g_sumP[t] = 0.f; g_sumM[t] = 0.f; }
    if (t < 64) g_pcnt[t] = 0;
}

// ---------------- kernel 1: gate ----------------
__global__ void __launch_bounds__(256) k_gate(const float* __restrict__ x,
                                              const float* __restrict__ gw,
                                              const float* __restrict__ gb) {
    __shared__ float sP[RR], sM[RR];
    int tid = threadIdx.x;
    if (tid < RR) { sP[tid] = 0.f; sM[tid] = 0.f; }
    __syncthreads();

    int warp = tid >> 5, lane = tid & 31;
    int b = blockIdx.x * 8 + warp;

    float acc[RR];
#pragma unroll
    for (int r = 0; r < RR; r++) acc[r] = 0.f;
    const float* xr = x + b * DD;
    for (int d = lane; d < DD; d += 32) {
        float xv = xr[d];
        const float4* g4 = (const float4*)(gw + d * RR);
        float4 a = g4[0], c = g4[1];
        acc[0] += xv * a.x; acc[1] += xv * a.y; acc[2] += xv * a.z; acc[3] += xv * a.w;
        acc[4] += xv * c.x; acc[5] += xv * c.y; acc[6] += xv * c.z; acc[7] += xv * c.w;
    }
#pragma unroll
    for (int r = 0; r < RR; r++)
#pragma unroll
        for (int o = 16; o; o >>= 1) acc[r] += __shfl_xor_sync(0xffffffffu, acc[r], o);

    if (lane == 0) {
        float lg[RR];
#pragma unroll
        for (int r = 0; r < RR; r++) lg[r] = acc[r] + gb[r];
        int i0 = 0; float v0 = lg[0];
#pragma unroll
        for (int r = 1; r < RR; r++) if (lg[r] > v0) { v0 = lg[r]; i0 = r; }
        int i1 = -1; float v1 = -3.0e38f;
#pragma unroll
        for (int r = 0; r < RR; r++) if (r != i0 && lg[r] > v1) { v1 = lg[r]; i1 = r; }

        float s = 0.f, pr[RR];
#pragma unroll
        for (int r = 0; r < RR; r++) { pr[r] = expf(lg[r] - v0); s += pr[r]; }
        float inv = 1.f / s;
#pragma unroll
        for (int r = 0; r < RR; r++) atomicAdd(&sP[r], pr[r] * inv);
        atomicAdd(&sM[i0], 1.f);
        atomicAdd(&sM[i1], 1.f);

        float e1 = expf(v1 - v0);
        float den = 1.f / (1.f + e1);
        g_gw[b * 2 + 0] = den;
        g_gw[b * 2 + 1] = e1 * den;

        int p0 = atomicAdd(&g_cnt[i0], 1); g_list[i0 * BB + p0] = b * 2 + 0;
        int p1 = atomicAdd(&g_cnt[i1], 1); g_list[i1 * BB + p1] = b * 2 + 1;

        int pid = i0 * 8 + i1;
        int pp = atomicAdd(&g_pcnt[pid], 1); g_plist[pid * BB + pp] = b;
    }
    __syncthreads();
    if (tid < RR) { atomicAdd(&g_sumP[tid], sP[tid]); atomicAdd(&g_sumM[tid], sM[tid]); }
}

// ---------------- kernel 2: scheduler (split-K, SM-affine scatter) ----------------
__global__ void k_sched() {
    __shared__ int list[GRID_UV];
    __shared__ int roff[RR], poff[64];
    int tid = threadIdx.x;
    for (int i = tid; i < GRID_UV; i += 256) list[i] = -1;
    for (int i = tid; i < GRID_MAIN; i += 256) g_ptile[i] = -1;
    __syncthreads();
    if (tid == 0) {
        int o = 256;     // xu entries start after 128 ev tiles x 2 halves
        for (int r = 0; r < RR; r++) { roff[r] = o; o += 2 * ((g_cnt[r] + 63) >> 6); }
        o = 0;
        for (int p = 0; p < 64; p++) { poff[p] = o; o += (g_pcnt[p] + 15) >> 4; }
    }
    __syncthreads();
    if (tid < 256) {
        int tile = tid >> 1, kh = tid & 1;
        int r = tile >> 4, ti = tile & 15;
        list[tid] = (r << 24) | (kh << 23) | ti;
    }
    if (tid < RR) {
        int r = tid;
        int n = (g_cnt[r] + 63) >> 6;
        for (int i = 0; i < n; i++) {
            list[roff[r] + 2 * i + 0] = (1 << 28) | (r << 24) | (0 << 23) | i;
            list[roff[r] + 2 * i + 1] = (1 << 28) | (r << 24) | (1 << 23) | i;
        }
    }
    if (tid >= 64 && tid < 128) {
        int p = tid - 64;
        int n = (g_pcnt[p] + 15) >> 4;
        for (int i = 0; i < n; i++) g_ptile[poff[p] + i] = (p << 16) | i;
    }
    __syncthreads();
    for (int bid = tid; bid < GRID_UV; bid += 256) {
        int sm = bid % 148, k = bid / 148;
        g_uvtile[bid] = list[sm * SLOTS + k];
    }
}

// ---------------- kernel 3: split-K ev/xu GEMM (128 thr, 64 rows x 64 h x 192 d) ----------------
__global__ void __launch_bounds__(128, 6) k_uv(const float* __restrict__ x,
                                               const float* __restrict__ re,
                                               const float* __restrict__ Uw,
                                               const float* __restrict__ Vw) {
    __shared__ float xT[DC * XSTR];   // transposed x chunk [d][row]  17.4 KB
    __shared__ int   s_code[64];

    int info = g_uvtile[blockIdx.x];
    if (info < 0) return;
    int type = (info >> 28) & 1;
    int r    = (info >> 24) & 15;
    int kh   = (info >> 23) & 1;
    int tile = info & 0x7fffff;
    int tid = threadIdx.x;

    const float* W = (type == 0 ? Vw : Uw) + r * DD * HH;

    if (tid < 64) {
        if (type == 0) s_code[tid] = tile * 64 + tid;
        else {
            int cnt = g_cnt[r], base = tile * 64;
            s_code[tid] = (base + tid < cnt) ? g_list[r * BB + base + tid] : -1;
        }
    }
    __syncthreads();

    int w = tid >> 5, l = tid & 31;
    int hq = l & 15, rg = l >> 4;
    int h0 = hq * 4;
    int wrow = w * 16 + rg * 8;          // 8 rows (4 f32x2 pairs) per lane

    int srow = tid & 63, shalf = tid >> 6;
    const float* src;
    {
        int c = s_code[srow];
        if (type == 0) src = re + (long)c * DD;
        else           src = (c >= 0) ? (x + (long)(c >> 1) * DD) : (const float*)0;
    }

    ull acc[4][4];
#pragma unroll
    for (int a = 0; a < 4; a++)
#pragma unroll
        for (int b = 0; b < 4; b++) acc[a][b] = 0ULL;

    int dbase = kh * 192;
    for (int cc = 0; cc < 3; cc++) {
        int dc = dbase + cc * DC;
        if (src) {
#pragma unroll
            for (int i = 0; i < 8; i++) {
                int d = shalf * 32 + i * 4;
                float4 v = __ldcs((const float4*)(src + dc + d));   // evict-first: keep W in L1
                xT[(d + 0) * XSTR + srow] = v.x; xT[(d + 1) * XSTR + srow] = v.y;
                xT[(d + 2) * XSTR + srow] = v.z; xT[(d + 3) * XSTR + srow] = v.w;
            }
        } else {
#pragma unroll
            for (int i = 0; i < 8; i++) {
                int d = shalf * 32 + i * 4;
                xT[(d + 0) * XSTR + srow] = 0.f; xT[(d + 1) * XSTR + srow] = 0.f;
                xT[(d + 2) * XSTR + srow] = 0.f; xT[(d + 3) * XSTR + srow] = 0.f;
            }
        }
        __syncthreads();

#pragma unroll 8
        for (int d = 0; d < DC; d++) {
            float4 wv = *(const float4*)(W + (dc + d) * HH + h0);
            ull b0 = pk2(wv.x, wv.x), b1 = pk2(wv.y, wv.y);
            ull b2 = pk2(wv.z, wv.z), b3 = pk2(wv.w, wv.w);
            ulonglong2 xA = *(const ulonglong2*)&xT[d * XSTR + wrow];       // LDS.128 broadcast
            ulonglong2 xB = *(const ulonglong2*)&xT[d * XSTR + wrow + 4];
            ull x0 = xA.x, x1 = xA.y, x2 = xB.x, x3 = xB.y;
            acc[0][0] = fma2(x0, b0, acc[0][0]); acc[0][1] = fma2(x0, b1, acc[0][1]);
            acc[0][2] = fma2(x0, b2, acc[0][2]); acc[0][3] = fma2(x0, b3, acc[0][3]);
            acc[1][0] = fma2(x1, b0, acc[1][0]); acc[1][1] = fma2(x1, b1, acc[1][1]);
            acc[1][2] = fma2(x1, b2, acc[1][2]); acc[1][3] = fma2(x1, b3, acc[1][3]);
            acc[2][0] = fma2(x2, b0, acc[2][0]); acc[2][1] = fma2(x2, b1, acc[2][1]);
            acc[2][2] = fma2(x2, b2, acc[2][2]); acc[2][3] = fma2(x2, b3, acc[2][3]);
            acc[3][0] = fma2(x3, b0, acc[3][0]); acc[3][1] = fma2(x3, b1, acc[3][1]);
            acc[3][2] = fma2(x3, b2, acc[3][2]); acc[3][3] = fma2(x3, b3, acc[3][3]);
        }
        __syncthreads();
    }

    // store raw partials (no reduction, no norm)
    float* pb = g_part + (long)kh * NROWS * HH;
#pragma unroll
    for (int rp = 0; rp < 4; rp++) {
        float4 lo4, hi4;
        float lo, hi;
        upk2(acc[rp][0], lo, hi); lo4.x = lo; hi4.x = hi;
        upk2(acc[rp][1], lo, hi); lo4.y = lo; hi4.y = hi;
        upk2(acc[rp][2], lo, hi); lo4.z = lo; hi4.z = hi;
        upk2(acc[rp][3], lo, hi); lo4.w = lo; hi4.w = hi;
        int row0 = wrow + 2 * rp;
        if (type == 0) {
            long g0 = r * 1024 + tile * 64 + row0;
            *(float4*)(pb + g0 * HH + h0)       = lo4;
            *(float4*)(pb + (g0 + 1) * HH + h0) = hi4;
        } else {
            int c0 = s_code[row0], c1 = s_code[row0 + 1];
            if (c0 >= 0) *(float4*)(pb + (8192L + c0) * HH + h0) = lo4;
            if (c1 >= 0) *(float4*)(pb + (8192L + c1) * HH + h0) = hi4;
        }
    }
}

// ---------------- kernel 3b: finish ev (combine halves + bias + norm + transpose) ----------------
__global__ void __launch_bounds__(256) k_fin_ev(const float* __restrict__ Vb) {
    __shared__ float outT[HH * XSTR];   // [h][row]
    __shared__ float s_rn[64];
    int b = blockIdx.x;                 // 0..127
    int r = b >> 4, ebase = (b & 15) * 64;
    int tid = threadIdx.x;
    int row = tid >> 2, q = tid & 3;
    long grow = r * 1024 + ebase + row;
    const float4* p0 = (const float4*)(g_part + grow * HH);
    const float4* p1 = (const float4*)(g_part + ((long)NROWS + grow) * HH);
    const float4* bb = (const float4*)(Vb + r * HH);

    float ss = 0.f;
    float4 vals[4];
#pragma unroll
    for (int i = 0; i < 4; i++) {
        int hq4 = q * 4 + i;
        float4 a = p0[hq4], c = p1[hq4], bi = bb[hq4];
        float4 v = make_float4(a.x + c.x + bi.x, a.y + c.y + bi.y,
                               a.z + c.z + bi.z, a.w + c.w + bi.w);
        vals[i] = v;
        ss += v.x * v.x + v.y * v.y + v.z * v.z + v.w * v.w;
    }
    ss += __shfl_xor_sync(0xffffffffu, ss, 1);
    ss += __shfl_xor_sync(0xffffffffu, ss, 2);
    if (q == 0) s_rn[row] = 1.f / fmaxf(sqrtf(ss), 1e-12f);
#pragma unroll
    for (int i = 0; i < 4; i++) {
        int h = (q * 4 + i) * 4;
        outT[(h + 0) * XSTR + row] = vals[i].x;
        outT[(h + 1) * XSTR + row] = vals[i].y;
        outT[(h + 2) * XSTR + row] = vals[i].z;
        outT[(h + 3) * XSTR + row] = vals[i].w;
    }
    __syncthreads();
    int h = tid >> 2, qq = tid & 3;
    float* dst = g_evt + (r * HH + h) * EE + ebase + qq * 16;
#pragma unroll
    for (int i = 0; i < 4; i++) {
        int e = qq * 16 + i * 4;
        float4 o = make_float4(outT[h * XSTR + e + 0] * s_rn[e + 0],
                               outT[h * XSTR + e + 1] * s_rn[e + 1],
                               outT[h * XSTR + e + 2] * s_rn[e + 2],
                               outT[h * XSTR + e + 3] * s_rn[e + 3]);
        *(float4*)(dst + i * 4) = o;
    }
}

// ---------------- kernel 4: pair-grouped scores + softmax + combine + sample ----------------
__global__ void __launch_bounds__(256, 2) k_main(const float* __restrict__ rnd,
                                                 const float* __restrict__ Ub,
                                                 float* __restrict__ out) {
    extern __shared__ float dyn[];
    float* p_s = dyn;                            // [16][1024]  64KB
    float* xu_s = dyn + 16 * EE;                 // [2][64][20] 10.2KB
    __shared__ int   s_b[16];
    __shared__ float s_w[2][16];
    __shared__ float red[8][16];
    __shared__ float s_scale[16];

    int info = g_ptile[blockIdx.x];
    if (info < 0) return;
    int pid = info >> 16, base = (info & 0xffff) * 16;
    int r0 = pid >> 3, r1 = pid & 7;
    int cnt = g_pcnt[pid];
    int nt = min(16, cnt - base);
    int tid = threadIdx.x;

    if (tid < 16) {
        int b = (tid < nt) ? g_plist[pid * BB + base + tid] : -1;
        s_b[tid] = b;
        s_w[0][tid] = (b >= 0) ? g_gw[b * 2 + 0] : 0.f;
        s_w[1][tid] = (b >= 0) ? g_gw[b * 2 + 1] : 0.f;
    }
    __syncthreads();
    {   // stage xu: combine split-K partials + bias, l2-normalize (8 threads/code)
        int s = tid >> 7, c = (tid >> 3) & 15, j = tid & 7, h0 = j * 8;
        int b = s_b[c];
        float* dst = xu_s + s * (HH * DPAD);
        float4 v0 = make_float4(0.f, 0.f, 0.f, 0.f), v1 = v0;
        float ss = 0.f;
        if (b >= 0) {
            long code = (long)b * 2 + s;
            const float4* p0 = (const float4*)(g_part + (8192L + code) * HH + h0);
            const float4* p1 = (const float4*)(g_part + ((long)NROWS + 8192L + code) * HH + h0);
            int rr = s ? r1 : r0;
            const float4* bb4 = (const float4*)(Ub + rr * HH + h0);
            float4 a0 = p0[0], a1 = p0[1];
            float4 c0 = p1[0], c1 = p1[1];
            float4 b0 = bb4[0], b1 = bb4[1];
            v0 = make_float4(a0.x + c0.x + b0.x, a0.y + c0.y + b0.y,
                             a0.z + c0.z + b0.z, a0.w + c0.w + b0.w);
            v1 = make_float4(a1.x + c1.x + b1.x, a1.y + c1.y + b1.y,
                             a1.z + c1.z + b1.z, a1.w + c1.w + b1.w);
            ss = v0.x * v0.x + v0.y * v0.y + v0.z * v0.z + v0.w * v0.w
               + v1.x * v1.x + v1.y * v1.y + v1.z * v1.z + v1.w * v1.w;
        }
#pragma unroll
        for (int o = 1; o < 8; o <<= 1) ss += __shfl_xor_sync(0xffffffffu, ss, o);
        float rn = 1.f / fmaxf(sqrtf(ss), 1e-12f);
        dst[(h0 + 0) * DPAD + c] = v0.x * rn; dst[(h0 + 1) * DPAD + c] = v0.y * rn;
        dst[(h0 + 2) * DPAD + c] = v0.z * rn; dst[(h0 + 3) * DPAD + c] = v0.w * rn;
        dst[(h0 + 4) * DPAD + c] = v1.x * rn; dst[(h0 + 5) * DPAD + c] = v1.y * rn;
        dst[(h0 + 6) * DPAD + c] = v1.z * rn; dst[(h0 + 7) * DPAD + c] = v1.w * rn;
    }
    __syncthreads();

    int e0 = tid * 4;
    int lane = tid & 31, w = tid >> 5;

    for (int ph = 0; ph < 2; ph++) {
        int r = ph ? r1 : r0;
        ull acc2[8][4];
#pragma unroll
        for (int tp = 0; tp < 8; tp++)
#pragma unroll
            for (int j = 0; j < 4; j++) acc2[tp][j] = 0ULL;

        const float* evr = g_evt + r * HH * EE;
        const float* xub = xu_s + ph * (HH * DPAD);

        float4 evn = *(const float4*)(evr + e0);   // prefetch h=0
#pragma unroll 4
        for (int h = 0; h < HH; h++) {
            float4 ev4 = evn;
            if (h + 1 < HH) evn = *(const float4*)(evr + (h + 1) * EE + e0);
            ull bx = pk2(ev4.x, ev4.x);
            ull by = pk2(ev4.y, ev4.y);
            ull bz = pk2(ev4.z, ev4.z);
            ull bw = pk2(ev4.w, ev4.w);
            const ulonglong2* xp2 = (const ulonglong2*)(xub + h * DPAD);   // LDS.128 broadcast
            ulonglong2 xa = xp2[0], xb2 = xp2[1], xc = xp2[2], xd = xp2[3];
            ull xs0 = xa.x, xs1 = xa.y, xs2 = xb2.x, xs3 = xb2.y;
            ull xs4 = xc.x, xs5 = xc.y, xs6 = xd.x, xs7 = xd.y;
            acc2[0][0] = fma2(xs0, bx, acc2[0][0]); acc2[0][1] = fma2(xs0, by, acc2[0][1]);
            acc2[0][2] = fma2(xs0, bz, acc2[0][2]); acc2[0][3] = fma2(xs0, bw, acc2[0][3]);
            acc2[1][0] = fma2(xs1, bx, acc2[1][0]); acc2[1][1] = fma2(xs1, by, acc2[1][1]);
            acc2[1][2] = fma2(xs1, bz, acc2[1][2]); acc2[1][3] = fma2(xs1, bw, acc2[1][3]);
            acc2[2][0] = fma2(xs2, bx, acc2[2][0]); acc2[2][1] = fma2(xs2, by, acc2[2][1]);
            acc2[2][2] = fma2(xs2, bz, acc2[2][2]); acc2[2][3] = fma2(xs2, bw, acc2[2][3]);
            acc2[3][0] = fma2(xs3, bx, acc2[3][0]); acc2[3][1] = fma2(xs3, by, acc2[3][1]);
            acc2[3][2] = fma2(xs3, bz, acc2[3][2]); acc2[3][3] = fma2(xs3, bw, acc2[3][3]);
            acc2[4][0] = fma2(xs4, bx, acc2[4][0]); acc2[4][1] = fma2(xs4, by, acc2[4][1]);
            acc2[4][2] = fma2(xs4, bz, acc2[4][2]); acc2[4][3] = fma2(xs4, bw, acc2[4][3]);
            acc2[5][0] = fma2(xs5, bx, acc2[5][0]); acc2[5][1] = fma2(xs5, by, acc2[5][1]);
            acc2[5][2] = fma2(xs5, bz, acc2[5][2]); acc2[5][3] = fma2(xs5, bw, acc2[5][3]);
            acc2[6][0] = fma2(xs6, bx, acc2[6][0]); acc2[6][1] = fma2(xs6, by, acc2[6][1]);
            acc2[6][2] = fma2(xs6, bz, acc2[6][2]); acc2[6][3] = fma2(xs6, bw, acc2[6][3]);
            acc2[7][0] = fma2(xs7, bx, acc2[7][0]); acc2[7][1] = fma2(xs7, by, acc2[7][1]);
            acc2[7][2] = fma2(xs7, bz, acc2[7][2]); acc2[7][3] = fma2(xs7, bw, acc2[7][3]);
        }

        // exp + row sum (no max subtraction: scores bounded by 1)
        {
            float lsum[16];
#pragma unroll
            for (int t = 0; t < 16; t++) lsum[t] = 0.f;
#pragma unroll
            for (int tp = 0; tp < 8; tp++) {
#pragma unroll
                for (int j = 0; j < 4; j++) {
                    float lo, hi;
                    upk2(acc2[tp][j], lo, hi);
                    float elo = __expf(lo);
                    float ehi = __expf(hi);
                    lsum[2 * tp]     += elo;
                    lsum[2 * tp + 1] += ehi;
                    acc2[tp][j] = pk2(elo, ehi);
                }
            }
#pragma unroll
            for (int t = 0; t < 16; t++)
#pragma unroll
                for (int o = 16; o; o >>= 1)
                    lsum[t] += __shfl_xor_sync(0xffffffffu, lsum[t], o);
            if (lane == 0)
#pragma unroll
                for (int t = 0; t < 16; t++) red[w][t] = lsum[t];
        }
        __syncthreads();
        if (tid < 16) {
            float s = 0.f;
#pragma unroll
            for (int ww = 0; ww < 8; ww++) s += red[ww][tid];
            s_scale[tid] = s_w[ph][tid] / s;
        }
        __syncthreads();

#pragma unroll
        for (int tp = 0; tp < 8; tp++) {
            int t0 = 2 * tp, t1 = 2 * tp + 1;
            float sc0 = s_scale[t0], sc1 = s_scale[t1];
            float4 olo, ohi;
            float lo, hi;
            upk2(acc2[tp][0], lo, hi); olo.x = lo * sc0; ohi.x = hi * sc1;
            upk2(acc2[tp][1], lo, hi); olo.y = lo * sc0; ohi.y = hi * sc1;
            upk2(acc2[tp][2], lo, hi); olo.z = lo * sc0; ohi.z = hi * sc1;
            upk2(acc2[tp][3], lo, hi); olo.w = lo * sc0; ohi.w = hi * sc1;
            float4* d0 = (float4*)(p_s + t0 * EE + e0);
            float4* d1 = (float4*)(p_s + t1 * EE + e0);
            if (ph == 0) {
                *d0 = olo; *d1 = ohi;
            } else {
                float4 a = *d0, c = *d1;
                a.x += olo.x; a.y += olo.y; a.z += olo.z; a.w += olo.w;
                c.x += ohi.x; c.y += ohi.y; c.z += ohi.z; c.w += ohi.w;
                *d0 = a; *d1 = c;
            }
        }
        __syncthreads();
    }

    // sampling: warp w handles tokens 2w, 2w+1
#pragma unroll
    for (int k = 0; k < 2; k++) {
        int t = w * 2 + k;
        int b = s_b[t];
        if (b < 0) continue;
        float rv = rnd[b];
        int ebase2 = lane * 32;
        float v[32];
        const float4* pr = (const float4*)(p_s + t * EE + ebase2);
#pragma unroll
        for (int q = 0; q < 8; q++) {
            float4 f = pr[q];
            v[q * 4 + 0] = f.x; v[q * 4 + 1] = f.y; v[q * 4 + 2] = f.z; v[q * 4 + 3] = f.w;
        }
        float lsum = 0.f;
#pragma unroll
        for (int i = 0; i < 32; i++) lsum += v[i];
        float sc = lsum;
#pragma unroll
        for (int o = 1; o < 32; o <<= 1) {
            float u = __shfl_up_sync(0xffffffffu, sc, o);
            if (lane >= o) sc += u;
        }
        float run = sc - lsum;
        int cand = 0x7fffffff;
        float pv = 0.f;
#pragma unroll
        for (int i = 0; i < 32; i++) {
            run += v[i];
            if (cand == 0x7fffffff && run > rv) { cand = ebase2 + i; pv = v[i]; }
        }
        unsigned mask = __ballot_sync(0xffffffffu, cand != 0x7fffffff);
        if (mask == 0) {
            if (lane == 0) { out[b] = 0.f; out[BB + b] = logf(v[0]); }
        } else {
            int firstlane = __ffs(mask) - 1;
            if (lane == firstlane) { out[b] = (float)cand; out[BB + b] = logf(pv); }
        }
    }
}

// ---------------- kernel 5: aux ----------------
__global__ void k_aux(float* __restrict__ out) {
    if (threadIdx.x == 0 && blockIdx.x == 0) {
        float s = 0.f;
#pragma unroll
        for (int r = 0; r < RR; r++) s += g_sumP[r] * g_sumM[r];
        out[2 * BB] = (float)RR * 0.05f * s / ((float)BB * (float)BB);
    }
}

// ---------------- launch ----------------
extern "C" void kernel_launch(void* const* d_in, const int* in_sizes, int n_in,
                              void* d_out, int out_size) {
    const float* x   = (const float*)d_in[0];
    const float* re  = (const float*)d_in[1];
    const float* rnd = (const float*)d_in[2];
    const float* gw  = (const float*)d_in[3];
    const float* gb  = (const float*)d_in[4];
    const float* Uw  = (const float*)d_in[5];
    const float* Ub  = (const float*)d_in[6];
    const float* Vw  = (const float*)d_in[7];
    const float* Vb  = (const float*)d_in[8];
    float* out = (float*)d_out;

    const int dyn_bytes = (16 * EE + 2 * HH * DPAD) * sizeof(float);  // ~74.2KB
    cudaFuncSetAttribute(k_main, cudaFuncAttributeMaxDynamicSharedMemorySize, dyn_bytes);

    k_init<<<1, 128>>>();
    k_gate<<<BB / 8, 256>>>(x, gw, gb);
    k_sched<<<1, 256>>>();
    k_uv<<<GRID_UV, 128>>>(x, re, Uw, Vw);
    k_fin_ev<<<128, 256>>>(Vb);
    k_main<<<GRID_MAIN, 256, dyn_bytes>>>(rnd, Ub, out);
    k_aux<<<1, 32>>>(out);
}